// round 16
// baseline (speedup 1.0000x reference)
#include <cuda_runtime.h>
#include <cstddef>
#include <cstdint>

// Problem constants (fixed by the reference setup)
#define BATCH 32
#define SEQ   512
#define DIM   1024
#define NCOLS (BATCH * DIM)   // 32768 independent columns
#define CHUNK 8               // scan steps per pipeline stage
#define STAGES 6              // per-warp smem ring depth (42 KB total)
#define NCHUNK (SEQ / CHUNK)  // 64
#define WARPS  7              // 224 threads / 32
#define NBLK   147            // 146 full blocks (224 cols) + 1 tail (64 cols)

// 1.0f / 0.001f correctly rounded = 999.99994f. For sp in {0,1},
// sp / 0.001f == sp * 999.99994f bitwise (1*c and 0*c are exact).
#define SPIKE_OUT 999.99994f

// Float-valued compare. Empirically the fastest exact form on this toolchain
// (r12: 29.1us vs ternary r13: 36.2us).
__device__ __forceinline__ float ge1(float a)
{
    float one;
    asm("set.ge.f32.f32 %0, %1, %2;" : "=f"(one) : "f"(a), "f"(1.0f));
    return one;
}

// One scan step = 4 substeps of {v += r; sp = floor(v); v -= sp;}, bitwise-
// faithful. With v in [0,1) and 0 <= r < 1:  a = v + r lies in [0, 2), so
// floor(a) == ge1(a) in {0.0f, 1.0f} and v' = a - ge1(a) is the literal
// reference subtraction. Only the LAST substep's spike survives.
__device__ __forceinline__ float step4(float& v, float r)
{
    #pragma unroll
    for (int i = 0; i < 3; ++i) {
        const float a = v + r;
        v = a - ge1(a);
    }
    const float a   = v + r;
    const float one = ge1(a);
    v = a - one;
    return one * SPIKE_OUT;      // off the chain
}

__global__ __launch_bounds__(224, 1)
void dual_threshold_scan_kernel(const float* __restrict__ inputs,
                                const float* __restrict__ init_state,
                                float* __restrict__ out)
{
    // Per-warp private ring: warp -> stage -> CHUNK rows x 32 cols. 42 KB.
    __shared__ float stage_buf[WARPS][STAGES][CHUNK][32];

    const int tid  = threadIdx.x;
    const int wid  = tid >> 5;
    const int lane = tid & 31;

    // Warp-uniform column base; tail block's upper warps exit as a unit.
    const int colbase = blockIdx.x * 224 + wid * 32;
    if (colbase >= NCOLS) return;

    // 32-aligned and 32 | 1024 => a warp's 32 cols stay inside one batch row.
    const int b = colbase >> 10;          // batch index
    const int d = colbase & (DIM - 1);    // dim offset of this warp's tile

    // Fetch role: 2 x 16B cp.async per lane per chunk. Round r (0..1):
    // lane L copies 16B of row (L>>3)+4r at float col (L&7)*4 of the tile.
    const int frow  = lane >> 3;          // 0..3
    const int fcol4 = (lane & 7) * 4;     // 16B-aligned float offset
    const float* fsrc = inputs + (size_t)b * SEQ * DIM + d + fcol4;

    float (&ring)[STAGES][CHUNK][32] = stage_buf[wid];

    auto issue_chunk = [&](int c) {
        const int st = c % STAGES;
        #pragma unroll
        for (int r = 0; r < 2; ++r) {
            const float* g = fsrc + (size_t)(c * CHUNK + frow + 4 * r) * DIM;
            uint32_t s = (uint32_t)__cvta_generic_to_shared(
                &ring[st][frow + 4 * r][fcol4]);
            asm volatile("cp.async.cg.shared.global [%0], [%1], 16;"
                         :: "r"(s), "l"(g));
        }
        asm volatile("cp.async.commit_group;" ::: "memory");
    };

    // Prologue: chunks 0..4 in flight (5 groups = STAGES-1).
    #pragma unroll
    for (int c = 0; c < STAGES - 1; ++c)
        issue_chunk(c);

    float* __restrict__ op = out + (size_t)b * SEQ * DIM + d + lane;
    float v = init_state[colbase + lane];

    // Rate double-buffer: chunk k's rates live in registers while chunk
    // k+1's are LDS-prefetched under the chain.
    float rr[2][CHUNK];

    auto load_rates = [&](float* dst, int c) {
        const int st = c % STAGES;
        #pragma unroll
        for (int j = 0; j < CHUNK; ++j)
            dst[j] = fmaxf(ring[st][j][lane], 0.0f) * 0.001f;   // relu * DT
    };

    // Preload chunk 0's rates. wait allow 3: 5 issued => chunks 0,1 complete.
    asm volatile("cp.async.wait_group 3;" ::: "memory");
    __syncwarp();
    load_rates(rr[0], 0);

    // One pipeline iteration: consume rr[cur] (chunk k), prefetch rr[nxt]
    // (chunk k+1), refill chunk k+STAGES-1.
    // Invariant at iter k's wait: issued = 5+k groups, allow 3 pending =>
    // chunks 0..k+1 complete (FIFO) — exactly what the k+1 LDS needs.
    // WAR: refill writes stage (k+5)%6 == (k-1)%6, last read at iter k-2's
    // LDS; the per-iter syncwarps order those reads before this write.
    auto pipe_iter = [&](int k, float* cur, float* nxt) {
        asm volatile("cp.async.wait_group 3;" ::: "memory");
        __syncwarp();

        if (k + 1 < NCHUNK) load_rates(nxt, k + 1);

        const int kn = k + STAGES - 1;
        if (kn < NCHUNK) issue_chunk(kn);
        else asm volatile("cp.async.commit_group;" ::: "memory");

        // Pure serial chain on register-resident rates; stores off-chain.
        // The LDS above drain underneath this (~450 cyc) chain.
        #pragma unroll
        for (int j = 0; j < CHUNK; ++j)
            __stcs(op + (size_t)(k * CHUNK + j) * DIM, step4(v, cur[j]));
    };

    // NCHUNK is even; unroll x2 so the rr buffer index is compile-time.
    for (int k = 0; k < NCHUNK; k += 2) {
        pipe_iter(k,     rr[0], rr[1]);
        pipe_iter(k + 1, rr[1], rr[0]);
    }
}

extern "C" void kernel_launch(void* const* d_in, const int* in_sizes, int n_in,
                              void* d_out, int out_size)
{
    const float* inputs     = (const float*)d_in[0];  // [32, 512, 1024] f32
    const float* init_state = (const float*)d_in[1];  // [32, 1024] f32
    float*       out        = (float*)d_out;          // [32, 512, 1024] f32

    (void)in_sizes; (void)n_in; (void)out_size;

    // 147 blocks x 224 threads: one wave across 147 SMs; 146 blocks cover
    // 224 columns each, block 146 covers the final 64 (upper warps exit).
    dual_threshold_scan_kernel<<<NBLK, 224>>>(inputs, init_state, out);
}